// round 9
// baseline (speedup 1.0000x reference)
#include <cuda_runtime.h>
#include <cuda_fp16.h>
#include <cstdint>

// Problem constants
#define MM      16
#define NN      8192
#define KK      8192
#define GROUPK  128
#define SPLITK  8
#define CHUNK   1024        // K per split = KK/SPLITK
#define NSTEPS  (KK / 16)   // 512 k16 steps

// Static device scratch (no allocation allowed)
__device__ float  g_part[SPLITK * MM * NN];        // 4 MB split-K partials
__device__ uint4  g_xfrag[NSTEPS * 32];            // 256 KB A fragments (fp16x2 x4)
__device__ float  g_scalesf[(KK / GROUPK) * NN];   // 2 MB normalized scales (fp32)
__device__ float  g_biasf[NN];                     // 32 KB normalized bias (fp32)

__device__ __forceinline__ float load_as_float(const void* p, int i, int dt)
{
    if (dt == 2) return ((const float*)p)[i];
    if (dt == 1) {
        const unsigned short b = ((const unsigned short*)p)[i];
        return __uint_as_float(((unsigned)b) << 16);
    }
    return __half2float(((const __half*)p)[i]);
}

// ---------------------------------------------------------------------------
// Convert: classify dtype per-block (from x's first 128 words), then
// scales/bias -> fp32 scratch; x -> A-fragment-major fp16 layout.
// Fragment layout: for k16-step t, lane l: g_xfrag[t*32+l] = {a0,a1,a2,a3}
// per the mma.m16n8k16 A-fragment mapping.
// ---------------------------------------------------------------------------
__global__ __launch_bounds__(256) void convert_kernel(
    const void* __restrict__ x, const void* __restrict__ sc,
    const void* __restrict__ bi)
{
    // ---- inline dtype classification (identical result in every block) ----
    __shared__ int s_lofl, s_small, s_dt;
    if (threadIdx.x == 0) { s_lofl = 0; s_small = 0; }
    __syncthreads();
    if (threadIdx.x < 128) {
        const unsigned w = ((const unsigned*)x)[threadIdx.x];
        const int e_lo = (w >> 7)  & 0xFF;
        const int e_hi = (w >> 23) & 0xFF;
        if (e_lo >= 100 && e_lo <= 135 && e_hi >= 100 && e_hi <= 135)
            atomicAdd(&s_lofl, 1);
        int sm = 0;
        if (((w >> 10) & 0x1F) <= 12) ++sm;
        if (((w >> 26) & 0x1F) <= 12) ++sm;
        if (sm) atomicAdd(&s_small, sm);
    }
    __syncthreads();
    if (threadIdx.x == 0) {
        int dt;
        if (s_lofl < 55)        dt = 2;              // fp32
        else if (s_small >= 13) dt = 0;              // fp16
        else                    dt = 1;              // bf16
        s_dt = dt;
    }
    __syncthreads();
    const int dt = s_dt;

    const int tid = blockIdx.x * blockDim.x + threadIdx.x;

    // A fragments: 512 steps * 32 lanes = 16384 threads
    if (tid < NSTEPS * 32) {
        const int t    = tid >> 5;
        const int lane = tid & 31;
        const int lr   = lane >> 2;
        const int lc   = lane & 3;
        const int kb   = t * 16;

        const int r0 = lr * KK, r1 = (lr + 8) * KK;
        const int ka = kb + 2 * lc;       // low k-pair
        const int kc = kb + 8 + 2 * lc;   // high k-pair

        __half2 h0 = __floats2half2_rn(load_as_float(x, r0 + ka, dt),
                                       load_as_float(x, r0 + ka + 1, dt));
        __half2 h1 = __floats2half2_rn(load_as_float(x, r1 + ka, dt),
                                       load_as_float(x, r1 + ka + 1, dt));
        __half2 h2 = __floats2half2_rn(load_as_float(x, r0 + kc, dt),
                                       load_as_float(x, r0 + kc + 1, dt));
        __half2 h3 = __floats2half2_rn(load_as_float(x, r1 + kc, dt),
                                       load_as_float(x, r1 + kc + 1, dt));
        uint4 v;
        v.x = *reinterpret_cast<unsigned*>(&h0);
        v.y = *reinterpret_cast<unsigned*>(&h1);
        v.z = *reinterpret_cast<unsigned*>(&h2);
        v.w = *reinterpret_cast<unsigned*>(&h3);
        g_xfrag[tid] = v;
    }

    // scales: 524288 elements
    if (tid < (KK / GROUPK) * NN)
        g_scalesf[tid] = load_as_float(sc, tid, dt);

    // bias: 8192 elements
    if (tid < NN)
        g_biasf[tid] = load_as_float(bi, tid, dt);
}

// ---------------------------------------------------------------------------
// Compute kernel: each warp computes a 16 x 32 output tile over one K-chunk.
// CTA = 4 warps -> 128 columns. grid = (NN/128, SPLITK).
// B distribution: NO shuffles. Each thread loads the qweight word for its own
// mma column (nb + 8*i + lane>>2); 4 lanes share each address (L1 broadcast),
// warp touches 8 consecutive words -> 1 sector per LDG, 8 independent
// loads per k16 step -> deep MLP.
// ---------------------------------------------------------------------------
__global__ __launch_bounds__(128) void quant_gemm_kernel(
    const unsigned* __restrict__ qw)     // [KK/8, NN] packed int4
{
    const int lane = threadIdx.x & 31;
    const int warp = threadIdx.x >> 5;
    const int lr   = lane >> 2;   // mma column within n8 tile / A row
    const int lc   = lane & 3;    // k-pair selector
    const int shft = lc * 8;      // byte select within packed word

    const int nb = blockIdx.x * 128 + warp * 32;   // warp's N base
    const int k0 = blockIdx.y * CHUNK;             // split's K base
    const int split = blockIdx.y;
    const int t0 = k0 >> 4;                        // first k16-step of split
    const int cbase = nb + lr;                     // this thread's column base

    const __half2 off1032 = __half2half2(__ushort_as_half(0x6408)); // 1032.0

    float acc[16];
    #pragma unroll
    for (int i = 0; i < 16; ++i) acc[i] = 0.f;

    for (int g = 0; g < CHUNK / GROUPK; ++g) {   // 8 groups of 128 k
        float grp[16];
        #pragma unroll
        for (int i = 0; i < 16; ++i) grp[i] = 0.f;

        #pragma unroll
        for (int s = 0; s < GROUPK / 16; ++s) {  // 8 x k16 steps
            const int kb = k0 + g * GROUPK + s * 16;
            const int kk = kb >> 3;              // qweight row (8 k per word)
            const size_t row0 = (size_t)kk * NN + cbase;
            const size_t row1 = row0 + NN;

            // 8 independent broadcast loads (1 sector each)
            unsigned q0[4], q1[4];
            #pragma unroll
            for (int i = 0; i < 4; ++i) {
                q0[i] = __ldg(&qw[row0 + 8 * i]);
                q1[i] = __ldg(&qw[row1 + 8 * i]);
            }

            // A fragment: one coalesced 16B load from fragment-major layout
            const uint4 av = g_xfrag[(t0 + g * 8 + s) * 32 + lane];

            #pragma unroll
            for (int i = 0; i < 4; ++i) {        // 4 x n8 tiles -> 32 columns
                const unsigned t0w = q0[i] >> shft;
                const unsigned t1w = q1[i] >> shft;

                // two nibbles -> fp16x2 {1024+lo,1024+hi}; -1032 -> (nib-8)
                unsigned h0 = (t0w & 0xFu) | ((t0w << 12) & 0xF0000u) | 0x64006400u;
                unsigned h1 = (t1w & 0xFu) | ((t1w << 12) & 0xF0000u) | 0x64006400u;
                __half2 bh0 = __hsub2(*reinterpret_cast<__half2*>(&h0), off1032);
                __half2 bh1 = __hsub2(*reinterpret_cast<__half2*>(&h1), off1032);
                const unsigned b0 = *reinterpret_cast<unsigned*>(&bh0);
                const unsigned b1 = *reinterpret_cast<unsigned*>(&bh1);

                asm volatile(
                    "mma.sync.aligned.m16n8k16.row.col.f32.f16.f16.f32 "
                    "{%0,%1,%2,%3}, {%4,%5,%6,%7}, {%8,%9}, {%0,%1,%2,%3};\n"
                    : "+f"(grp[4 * i + 0]), "+f"(grp[4 * i + 1]),
                      "+f"(grp[4 * i + 2]), "+f"(grp[4 * i + 3])
                    : "r"(av.x), "r"(av.y), "r"(av.z), "r"(av.w),
                      "r"(b0), "r"(b1));
            }
        }

        // Apply per-group scales (deferred): acc += grp * scale[g][col]
        const int gg = (k0 >> 7) + g;
        #pragma unroll
        for (int i = 0; i < 4; ++i) {
            const int cb = nb + 8 * i + lc * 2;  // this thread's two C columns
            const float2 sf = *reinterpret_cast<const float2*>(
                &g_scalesf[(size_t)gg * NN + cb]);
            acc[4 * i + 0] += grp[4 * i + 0] * sf.x;
            acc[4 * i + 1] += grp[4 * i + 1] * sf.y;
            acc[4 * i + 2] += grp[4 * i + 2] * sf.x;
            acc[4 * i + 3] += grp[4 * i + 3] * sf.y;
        }
    }

    // Store fp32 partials (each slot written exactly once)
    #pragma unroll
    for (int i = 0; i < 4; ++i) {
        const int cb = nb + 8 * i + lc * 2;
        float* p0 = &g_part[((size_t)split * MM + lr) * NN + cb];
        float* p1 = &g_part[((size_t)split * MM + lr + 8) * NN + cb];
        *reinterpret_cast<float2*>(p0) = make_float2(acc[4 * i + 0], acc[4 * i + 1]);
        *reinterpret_cast<float2*>(p1) = make_float2(acc[4 * i + 2], acc[4 * i + 3]);
    }
}

// ---------------------------------------------------------------------------
// Epilogue: sum SPLITK partials + bias -> FLOAT32 output.
// float4 per thread: 8 x LDG.128 in flight per thread.
// ---------------------------------------------------------------------------
__global__ __launch_bounds__(256) void reduce_kernel(float* __restrict__ out)
{
    const int idx = (blockIdx.x * blockDim.x + threadIdx.x) * 4;  // 0..MM*NN-4
    const int n   = idx & (NN - 1);

    const float4 b4 = *reinterpret_cast<const float4*>(&g_biasf[n]);
    float a0 = b4.x, a1 = b4.y, a2 = b4.z, a3 = b4.w;

    #pragma unroll
    for (int s = 0; s < SPLITK; ++s) {
        const float4 p = *reinterpret_cast<const float4*>(
            &g_part[(size_t)s * MM * NN + idx]);
        a0 += p.x; a1 += p.y; a2 += p.z; a3 += p.w;
    }
    *reinterpret_cast<float4*>(&out[idx]) = make_float4(a0, a1, a2, a3);
}

extern "C" void kernel_launch(void* const* d_in, const int* in_sizes, int n_in,
                              void* d_out, int out_size)
{
    // Bind inputs by UNIQUE element counts (order-proof):
    //   x: 131072, qweight: 8388608, scales: 524288, bias: 8192
    const void*     x      = nullptr;
    const unsigned* qw     = nullptr;
    const void*     scales = nullptr;
    const void*     bias   = nullptr;

    for (int i = 0; i < n_in; ++i) {
        switch (in_sizes[i]) {
            case MM * KK:            x      = d_in[i];                  break;
            case (KK / 8) * NN:      qw     = (const unsigned*)d_in[i]; break;
            case (KK / GROUPK) * NN: scales = d_in[i];                  break;
            case NN:                 bias   = d_in[i];                  break;
            default: break;
        }
    }
    if (!x || !qw || !scales || !bias) {
        x      = d_in[0];
        qw     = (const unsigned*)d_in[1];
        scales = d_in[2];
        bias   = d_in[3];
    }

    float* out = (float*)d_out;

    convert_kernel<<<(KK / GROUPK) * NN / 256, 256>>>(x, scales, bias);
    quant_gemm_kernel<<<dim3(NN / 128, SPLITK), 128>>>(qw);
    reduce_kernel<<<(MM * NN) / (256 * 4), 256>>>(out);
}

// round 11
// speedup vs baseline: 1.1067x; 1.1067x over previous
#include <cuda_runtime.h>
#include <cuda_fp16.h>
#include <cstdint>

// Problem constants
#define MM      16
#define NN      8192
#define KK      8192
#define GROUPK  128
#define SPLITK  16
#define CHUNK   512         // K per split = KK/SPLITK
#define NSTEPS  (KK / 16)   // 512 k16 steps

// Static device scratch (no allocation allowed)
__device__ float  g_part[SPLITK * MM * NN];        // 8 MB split-K partials
__device__ uint4  g_xfrag[NSTEPS * 32];            // 256 KB A fragments (fp16x2 x4)
__device__ float  g_scalesf[(KK / GROUPK) * NN];   // 2 MB normalized scales (fp32)
__device__ float  g_biasf[NN];                     // 32 KB normalized bias (fp32)
__device__ int    g_dtype;                         // 0=fp16, 1=bf16, 2=fp32

__device__ __forceinline__ float load_as_float(const void* p, int i, int dt)
{
    if (dt == 2) return ((const float*)p)[i];
    if (dt == 1) {
        const unsigned short b = ((const unsigned short*)p)[i];
        return __uint_as_float(((unsigned)b) << 16);
    }
    return __half2float(((const __half*)p)[i]);
}

// ---------------------------------------------------------------------------
// Convert: warp-0 ballot classify (cheap), then:
//   - x -> A-fragment-major fp16 layout (always; 16384 threads)
//   - scales/bias -> fp32 scratch ONLY if source is not already fp32
//     (fp32 source is read directly by gemm/reduce via g_dtype select)
// ---------------------------------------------------------------------------
__global__ __launch_bounds__(256) void convert_kernel(
    const void* __restrict__ x, const void* __restrict__ sc,
    const void* __restrict__ bi)
{
    __shared__ int s_dt;
    if (threadIdx.x < 32) {
        const unsigned lane = threadIdx.x;
        const unsigned w0 = ((const unsigned*)x)[lane];
        const unsigned w1 = ((const unsigned*)x)[32 + lane];

        // word-test: both 16-bit halves look like mid-exponent fp32-ish fields
        auto wordtest = [](unsigned w) -> bool {
            const int e_lo = (w >> 7)  & 0xFF;
            const int e_hi = (w >> 23) & 0xFF;
            return e_lo >= 100 && e_lo <= 135 && e_hi >= 100 && e_hi <= 135;
        };
        const int lofl = __popc(__ballot_sync(0xffffffffu, wordtest(w0)))
                       + __popc(__ballot_sync(0xffffffffu, wordtest(w1)));

        // small-test: fp16-decoded |v| < 0.25 count over 128 halves
        int sm = 0;
        if (((w0 >> 10) & 0x1F) <= 12) ++sm;
        if (((w0 >> 26) & 0x1F) <= 12) ++sm;
        if (((w1 >> 10) & 0x1F) <= 12) ++sm;
        if (((w1 >> 26) & 0x1F) <= 12) ++sm;
        const int small = __reduce_add_sync(0xffffffffu, sm);

        if (lane == 0) {
            int dt;
            if (lofl < 27)        dt = 2;   // fp32 (~9/64 pass)
            else if (small >= 8)  dt = 0;   // fp16 (~30/128)
            else                  dt = 1;   // bf16 (~0/128)
            s_dt = dt;
            if (blockIdx.x == 0) g_dtype = dt;
        }
    }
    __syncthreads();
    const int dt = s_dt;

    const int tid = blockIdx.x * blockDim.x + threadIdx.x;

    // A fragments: 512 steps * 32 lanes = 16384 threads
    if (tid < NSTEPS * 32) {
        const int t    = tid >> 5;
        const int lane = tid & 31;
        const int lr   = lane >> 2;
        const int lc   = lane & 3;
        const int kb   = t * 16;

        const int r0 = lr * KK, r1 = (lr + 8) * KK;
        const int ka = kb + 2 * lc;       // low k-pair
        const int kc = kb + 8 + 2 * lc;   // high k-pair

        __half2 h0 = __floats2half2_rn(load_as_float(x, r0 + ka, dt),
                                       load_as_float(x, r0 + ka + 1, dt));
        __half2 h1 = __floats2half2_rn(load_as_float(x, r1 + ka, dt),
                                       load_as_float(x, r1 + ka + 1, dt));
        __half2 h2 = __floats2half2_rn(load_as_float(x, r0 + kc, dt),
                                       load_as_float(x, r0 + kc + 1, dt));
        __half2 h3 = __floats2half2_rn(load_as_float(x, r1 + kc, dt),
                                       load_as_float(x, r1 + kc + 1, dt));
        uint4 v;
        v.x = *reinterpret_cast<unsigned*>(&h0);
        v.y = *reinterpret_cast<unsigned*>(&h1);
        v.z = *reinterpret_cast<unsigned*>(&h2);
        v.w = *reinterpret_cast<unsigned*>(&h3);
        g_xfrag[tid] = v;
    }

    // Scales/bias conversion only needed when source is 16-bit
    if (dt != 2) {
        const int stride = gridDim.x * blockDim.x;
        for (int i = tid; i < (KK / GROUPK) * NN; i += stride)
            g_scalesf[i] = load_as_float(sc, i, dt);
        for (int i = tid; i < NN; i += stride)
            g_biasf[i] = load_as_float(bi, i, dt);
    }
}

// ---------------------------------------------------------------------------
// Compute kernel: each warp computes a 16 x 32 output tile over one K-chunk.
// CTA = 4 warps -> 128 columns. grid = (NN/128, SPLITK) = 1024 CTAs.
// B: direct per-thread broadcast loads (no shuffles), 8 independent 1-sector
// LDGs per k16 step.
// ---------------------------------------------------------------------------
__global__ __launch_bounds__(128) void quant_gemm_kernel(
    const unsigned* __restrict__ qw,     // [KK/8, NN] packed int4
    const float* __restrict__ sc_src)    // scales source if fp32
{
    const int lane = threadIdx.x & 31;
    const int warp = threadIdx.x >> 5;
    const int lr   = lane >> 2;   // mma column within n8 tile / A row
    const int lc   = lane & 3;    // k-pair selector
    const int shft = lc * 8;      // byte select within packed word

    const int nb = blockIdx.x * 128 + warp * 32;   // warp's N base
    const int k0 = blockIdx.y * CHUNK;             // split's K base
    const int split = blockIdx.y;
    const int t0 = k0 >> 4;                        // first k16-step of split
    const int cbase = nb + lr;                     // this thread's column base

    const float* scp = (g_dtype == 2) ? sc_src : g_scalesf;

    const __half2 off1032 = __half2half2(__ushort_as_half(0x6408)); // 1032.0

    float acc[16];
    #pragma unroll
    for (int i = 0; i < 16; ++i) acc[i] = 0.f;

    for (int g = 0; g < CHUNK / GROUPK; ++g) {   // 4 groups of 128 k
        float grp[16];
        #pragma unroll
        for (int i = 0; i < 16; ++i) grp[i] = 0.f;

        #pragma unroll
        for (int s = 0; s < GROUPK / 16; ++s) {  // 8 x k16 steps
            const int kb = k0 + g * GROUPK + s * 16;
            const int kk = kb >> 3;              // qweight row (8 k per word)
            const size_t row0 = (size_t)kk * NN + cbase;
            const size_t row1 = row0 + NN;

            // 8 independent broadcast loads (1 sector each)
            unsigned q0[4], q1[4];
            #pragma unroll
            for (int i = 0; i < 4; ++i) {
                q0[i] = __ldg(&qw[row0 + 8 * i]);
                q1[i] = __ldg(&qw[row1 + 8 * i]);
            }

            // A fragment: one coalesced 16B load from fragment-major layout
            const uint4 av = g_xfrag[(t0 + g * 8 + s) * 32 + lane];

            #pragma unroll
            for (int i = 0; i < 4; ++i) {        // 4 x n8 tiles -> 32 columns
                const unsigned t0w = q0[i] >> shft;
                const unsigned t1w = q1[i] >> shft;

                // two nibbles -> fp16x2 {1024+lo,1024+hi}; -1032 -> (nib-8)
                unsigned h0 = (t0w & 0xFu) | ((t0w << 12) & 0xF0000u) | 0x64006400u;
                unsigned h1 = (t1w & 0xFu) | ((t1w << 12) & 0xF0000u) | 0x64006400u;
                __half2 bh0 = __hsub2(*reinterpret_cast<__half2*>(&h0), off1032);
                __half2 bh1 = __hsub2(*reinterpret_cast<__half2*>(&h1), off1032);
                const unsigned b0 = *reinterpret_cast<unsigned*>(&bh0);
                const unsigned b1 = *reinterpret_cast<unsigned*>(&bh1);

                asm volatile(
                    "mma.sync.aligned.m16n8k16.row.col.f32.f16.f16.f32 "
                    "{%0,%1,%2,%3}, {%4,%5,%6,%7}, {%8,%9}, {%0,%1,%2,%3};\n"
                    : "+f"(grp[4 * i + 0]), "+f"(grp[4 * i + 1]),
                      "+f"(grp[4 * i + 2]), "+f"(grp[4 * i + 3])
                    : "r"(av.x), "r"(av.y), "r"(av.z), "r"(av.w),
                      "r"(b0), "r"(b1));
            }
        }

        // Apply per-group scales (deferred): acc += grp * scale[g][col]
        const int gg = (k0 >> 7) + g;
        #pragma unroll
        for (int i = 0; i < 4; ++i) {
            const int cb = nb + 8 * i + lc * 2;  // this thread's two C columns
            const float2 sf = *reinterpret_cast<const float2*>(
                &scp[(size_t)gg * NN + cb]);
            acc[4 * i + 0] += grp[4 * i + 0] * sf.x;
            acc[4 * i + 1] += grp[4 * i + 1] * sf.y;
            acc[4 * i + 2] += grp[4 * i + 2] * sf.x;
            acc[4 * i + 3] += grp[4 * i + 3] * sf.y;
        }
    }

    // Store fp32 partials (each slot written exactly once)
    #pragma unroll
    for (int i = 0; i < 4; ++i) {
        const int cb = nb + 8 * i + lc * 2;
        float* p0 = &g_part[((size_t)split * MM + lr) * NN + cb];
        float* p1 = &g_part[((size_t)split * MM + lr + 8) * NN + cb];
        *reinterpret_cast<float2*>(p0) = make_float2(acc[4 * i + 0], acc[4 * i + 1]);
        *reinterpret_cast<float2*>(p1) = make_float2(acc[4 * i + 2], acc[4 * i + 3]);
    }
}

// ---------------------------------------------------------------------------
// Epilogue: sum SPLITK partials + bias -> FLOAT32 output.
// float4 per thread: 16 x LDG.128 in flight (L2-resident partials).
// ---------------------------------------------------------------------------
__global__ __launch_bounds__(256) void reduce_kernel(
    float* __restrict__ out, const float* __restrict__ bi_src)
{
    const int idx = (blockIdx.x * blockDim.x + threadIdx.x) * 4;  // 0..MM*NN-4
    const int n   = idx & (NN - 1);

    const float* bp = (g_dtype == 2) ? bi_src : g_biasf;
    const float4 b4 = *reinterpret_cast<const float4*>(&bp[n]);
    float a0 = b4.x, a1 = b4.y, a2 = b4.z, a3 = b4.w;

    #pragma unroll
    for (int s = 0; s < SPLITK; ++s) {
        const float4 p = *reinterpret_cast<const float4*>(
            &g_part[(size_t)s * MM * NN + idx]);
        a0 += p.x; a1 += p.y; a2 += p.z; a3 += p.w;
    }
    *reinterpret_cast<float4*>(&out[idx]) = make_float4(a0, a1, a2, a3);
}

extern "C" void kernel_launch(void* const* d_in, const int* in_sizes, int n_in,
                              void* d_out, int out_size)
{
    // Bind inputs by UNIQUE element counts (order-proof):
    //   x: 131072, qweight: 8388608, scales: 524288, bias: 8192
    const void*     x      = nullptr;
    const unsigned* qw     = nullptr;
    const void*     scales = nullptr;
    const void*     bias   = nullptr;

    for (int i = 0; i < n_in; ++i) {
        switch (in_sizes[i]) {
            case MM * KK:            x      = d_in[i];                  break;
            case (KK / 8) * NN:      qw     = (const unsigned*)d_in[i]; break;
            case (KK / GROUPK) * NN: scales = d_in[i];                  break;
            case NN:                 bias   = d_in[i];                  break;
            default: break;
        }
    }
    if (!x || !qw || !scales || !bias) {
        x      = d_in[0];
        qw     = (const unsigned*)d_in[1];
        scales = d_in[2];
        bias   = d_in[3];
    }

    float* out = (float*)d_out;

    convert_kernel<<<256, 256>>>(x, scales, bias);
    quant_gemm_kernel<<<dim3(NN / 128, SPLITK), 128>>>(qw, (const float*)scales);
    reduce_kernel<<<(MM * NN) / (256 * 4), 256>>>(out, (const float*)bias);
}

// round 13
// speedup vs baseline: 1.2837x; 1.1599x over previous
#include <cuda_runtime.h>
#include <cuda_fp16.h>
#include <cstdint>

// Problem constants
#define MM      16
#define NN      8192
#define KK      8192
#define GROUPK  128
#define SPLITK  16
#define CHUNK   512         // K per split = KK/SPLITK
#define NSTEPS  (KK / 16)   // 512 k16 steps

// Static device scratch (no allocation allowed)
__device__ uint4  g_xfrag[NSTEPS * 32];            // 256 KB A fragments (fp16x2 x4)
__device__ float  g_scalesf[(KK / GROUPK) * NN];   // 2 MB scales (only if src 16-bit)
__device__ int    g_dtype;                         // 0=fp16, 1=bf16, 2=fp32

__device__ __forceinline__ float load_as_float(const void* p, int i, int dt)
{
    if (dt == 2) return ((const float*)p)[i];
    if (dt == 1) {
        const unsigned short b = ((const unsigned short*)p)[i];
        return __uint_as_float(((unsigned)b) << 16);
    }
    return __half2float(((const __half*)p)[i]);
}

// ---------------------------------------------------------------------------
// Prep kernel (one launch):
//  1. classify input dtype (warp-0 ballot over x's first 64 words)
//  2. build A-fragment-major fp16 layout from x   (tids 0..16383)
//  3. initialize out = bias (float4 per thread, all 32768 tids)
//  4. convert scales to fp32 scratch ONLY if source is 16-bit
// ---------------------------------------------------------------------------
__global__ __launch_bounds__(256) void prep_kernel(
    const void* __restrict__ x, const void* __restrict__ sc,
    const void* __restrict__ bi, float* __restrict__ out)
{
    __shared__ int s_dt;
    if (threadIdx.x < 32) {
        const unsigned lane = threadIdx.x;
        const unsigned w0 = ((const unsigned*)x)[lane];
        const unsigned w1 = ((const unsigned*)x)[32 + lane];

        auto wordtest = [](unsigned w) -> bool {
            const int e_lo = (w >> 7)  & 0xFF;
            const int e_hi = (w >> 23) & 0xFF;
            return e_lo >= 100 && e_lo <= 135 && e_hi >= 100 && e_hi <= 135;
        };
        const int lofl = __popc(__ballot_sync(0xffffffffu, wordtest(w0)))
                       + __popc(__ballot_sync(0xffffffffu, wordtest(w1)));

        int sm = 0;
        if (((w0 >> 10) & 0x1F) <= 12) ++sm;
        if (((w0 >> 26) & 0x1F) <= 12) ++sm;
        if (((w1 >> 10) & 0x1F) <= 12) ++sm;
        if (((w1 >> 26) & 0x1F) <= 12) ++sm;
        const int small = __reduce_add_sync(0xffffffffu, sm);

        if (lane == 0) {
            int dt;
            if (lofl < 27)        dt = 2;   // fp32
            else if (small >= 8)  dt = 0;   // fp16
            else                  dt = 1;   // bf16
            s_dt = dt;
            if (blockIdx.x == 0) g_dtype = dt;
        }
    }
    __syncthreads();
    const int dt = s_dt;

    const int tid = blockIdx.x * blockDim.x + threadIdx.x;   // 0..32767

    // ---- A fragments: 512 steps * 32 lanes = 16384 threads ----
    if (tid < NSTEPS * 32) {
        const int t    = tid >> 5;
        const int lane = tid & 31;
        const int lr   = lane >> 2;
        const int lc   = lane & 3;
        const int kb   = t * 16;

        const int r0 = lr * KK, r1 = (lr + 8) * KK;
        const int ka = kb + 2 * lc;       // low k-pair (even)
        const int kc = kb + 8 + 2 * lc;   // high k-pair (even)

        __half2 h0, h1, h2, h3;
        if (dt == 2) {
            const float2* x2 = (const float2*)x;
            const float2 p0 = x2[(r0 + ka) >> 1];
            const float2 p1 = x2[(r1 + ka) >> 1];
            const float2 p2 = x2[(r0 + kc) >> 1];
            const float2 p3 = x2[(r1 + kc) >> 1];
            h0 = __floats2half2_rn(p0.x, p0.y);
            h1 = __floats2half2_rn(p1.x, p1.y);
            h2 = __floats2half2_rn(p2.x, p2.y);
            h3 = __floats2half2_rn(p3.x, p3.y);
        } else {
            h0 = __floats2half2_rn(load_as_float(x, r0 + ka, dt),
                                   load_as_float(x, r0 + ka + 1, dt));
            h1 = __floats2half2_rn(load_as_float(x, r1 + ka, dt),
                                   load_as_float(x, r1 + ka + 1, dt));
            h2 = __floats2half2_rn(load_as_float(x, r0 + kc, dt),
                                   load_as_float(x, r0 + kc + 1, dt));
            h3 = __floats2half2_rn(load_as_float(x, r1 + kc, dt),
                                   load_as_float(x, r1 + kc + 1, dt));
        }
        uint4 v;
        v.x = *reinterpret_cast<unsigned*>(&h0);
        v.y = *reinterpret_cast<unsigned*>(&h1);
        v.z = *reinterpret_cast<unsigned*>(&h2);
        v.w = *reinterpret_cast<unsigned*>(&h3);
        g_xfrag[tid] = v;
    }

    // ---- out = bias : 32768 threads x float4 = 131072 elements ----
    {
        const int idx = tid * 4;
        const int n   = idx & (NN - 1);
        float4 b4;
        if (dt == 2) {
            b4 = *reinterpret_cast<const float4*>(&((const float*)bi)[n]);
        } else {
            b4 = make_float4(load_as_float(bi, n, dt),
                             load_as_float(bi, n + 1, dt),
                             load_as_float(bi, n + 2, dt),
                             load_as_float(bi, n + 3, dt));
        }
        *reinterpret_cast<float4*>(&out[idx]) = b4;
    }

    // ---- scales conversion only when source is 16-bit ----
    if (dt != 2) {
        const int stride = gridDim.x * blockDim.x;
        for (int i = tid; i < (KK / GROUPK) * NN; i += stride)
            g_scalesf[i] = load_as_float(sc, i, dt);
    }
}

// ---------------------------------------------------------------------------
// GEMM: each warp computes a 16 x 32 output tile over one K-chunk and
// accumulates it directly into out via vectorized fp32 atomic reductions.
// CTA = 4 warps -> 128 columns. grid = (NN/128, SPLITK) = 1024 CTAs.
// ---------------------------------------------------------------------------
__global__ __launch_bounds__(128) void quant_gemm_kernel(
    const unsigned* __restrict__ qw,     // [KK/8, NN] packed int4
    const float* __restrict__ sc_src,    // scales source if fp32
    float* __restrict__ out)
{
    const int lane = threadIdx.x & 31;
    const int warp = threadIdx.x >> 5;
    const int lr   = lane >> 2;   // mma column within n8 tile / A row
    const int lc   = lane & 3;    // k-pair selector
    const int shft = lc * 8;      // byte select within packed word

    const int nb = blockIdx.x * 128 + warp * 32;   // warp's N base
    const int k0 = blockIdx.y * CHUNK;             // split's K base
    const int t0 = k0 >> 4;                        // first k16-step of split
    const int cbase = nb + lr;                     // this thread's column base

    const float* scp = (g_dtype == 2) ? sc_src : g_scalesf;

    const __half2 off1032 = __half2half2(__ushort_as_half(0x6408)); // 1032.0

    float acc[16];
    #pragma unroll
    for (int i = 0; i < 16; ++i) acc[i] = 0.f;

    for (int g = 0; g < CHUNK / GROUPK; ++g) {   // 4 groups of 128 k
        float grp[16];
        #pragma unroll
        for (int i = 0; i < 16; ++i) grp[i] = 0.f;

        #pragma unroll
        for (int s = 0; s < GROUPK / 16; ++s) {  // 8 x k16 steps
            const int kb = k0 + g * GROUPK + s * 16;
            const int kk = kb >> 3;              // qweight row (8 k per word)
            const size_t row0 = (size_t)kk * NN + cbase;
            const size_t row1 = row0 + NN;

            // 8 independent broadcast loads (1 sector each)
            unsigned q0[4], q1[4];
            #pragma unroll
            for (int i = 0; i < 4; ++i) {
                q0[i] = __ldg(&qw[row0 + 8 * i]);
                q1[i] = __ldg(&qw[row1 + 8 * i]);
            }

            // A fragment: one coalesced 16B load from fragment-major layout
            const uint4 av = g_xfrag[(t0 + g * 8 + s) * 32 + lane];

            #pragma unroll
            for (int i = 0; i < 4; ++i) {        // 4 x n8 tiles -> 32 columns
                const unsigned t0w = q0[i] >> shft;
                const unsigned t1w = q1[i] >> shft;

                // two nibbles -> fp16x2 {1024+lo,1024+hi}; -1032 -> (nib-8)
                unsigned h0 = (t0w & 0xFu) | ((t0w << 12) & 0xF0000u) | 0x64006400u;
                unsigned h1 = (t1w & 0xFu) | ((t1w << 12) & 0xF0000u) | 0x64006400u;
                __half2 bh0 = __hsub2(*reinterpret_cast<__half2*>(&h0), off1032);
                __half2 bh1 = __hsub2(*reinterpret_cast<__half2*>(&h1), off1032);
                const unsigned b0 = *reinterpret_cast<unsigned*>(&bh0);
                const unsigned b1 = *reinterpret_cast<unsigned*>(&bh1);

                asm volatile(
                    "mma.sync.aligned.m16n8k16.row.col.f32.f16.f16.f32 "
                    "{%0,%1,%2,%3}, {%4,%5,%6,%7}, {%8,%9}, {%0,%1,%2,%3};\n"
                    : "+f"(grp[4 * i + 0]), "+f"(grp[4 * i + 1]),
                      "+f"(grp[4 * i + 2]), "+f"(grp[4 * i + 3])
                    : "r"(av.x), "r"(av.y), "r"(av.z), "r"(av.w),
                      "r"(b0), "r"(b1));
            }
        }

        // Apply per-group scales (deferred): acc += grp * scale[g][col]
        const int gg = (k0 >> 7) + g;
        #pragma unroll
        for (int i = 0; i < 4; ++i) {
            const int cb = nb + 8 * i + lc * 2;  // this thread's two C columns
            const float2 sf = *reinterpret_cast<const float2*>(
                &scp[(size_t)gg * NN + cb]);
            acc[4 * i + 0] += grp[4 * i + 0] * sf.x;
            acc[4 * i + 1] += grp[4 * i + 1] * sf.y;
            acc[4 * i + 2] += grp[4 * i + 2] * sf.x;
            acc[4 * i + 3] += grp[4 * i + 3] * sf.y;
        }
    }

    // Accumulate directly into out (bias pre-loaded by prep_kernel).
    // Vectorized fp32 reductions: 8 x red.global.add.v2.f32 per thread.
    #pragma unroll
    for (int i = 0; i < 4; ++i) {
        const int cb = nb + 8 * i + lc * 2;
        float* p0 = &out[lr * NN + cb];
        float* p1 = &out[(lr + 8) * NN + cb];
        asm volatile("red.global.add.v2.f32 [%0], {%1, %2};"
                     :: "l"(p0), "f"(acc[4 * i + 0]), "f"(acc[4 * i + 1])
                     : "memory");
        asm volatile("red.global.add.v2.f32 [%0], {%1, %2};"
                     :: "l"(p1), "f"(acc[4 * i + 2]), "f"(acc[4 * i + 3])
                     : "memory");
    }
}

extern "C" void kernel_launch(void* const* d_in, const int* in_sizes, int n_in,
                              void* d_out, int out_size)
{
    // Bind inputs by UNIQUE element counts (order-proof):
    //   x: 131072, qweight: 8388608, scales: 524288, bias: 8192
    const void*     x      = nullptr;
    const unsigned* qw     = nullptr;
    const void*     scales = nullptr;
    const void*     bias   = nullptr;

    for (int i = 0; i < n_in; ++i) {
        switch (in_sizes[i]) {
            case MM * KK:            x      = d_in[i];                  break;
            case (KK / 8) * NN:      qw     = (const unsigned*)d_in[i]; break;
            case (KK / GROUPK) * NN: scales = d_in[i];                  break;
            case NN:                 bias   = d_in[i];                  break;
            default: break;
        }
    }
    if (!x || !qw || !scales || !bias) {
        x      = d_in[0];
        qw     = (const unsigned*)d_in[1];
        scales = d_in[2];
        bias   = d_in[3];
    }

    float* out = (float*)d_out;

    prep_kernel<<<128, 256>>>(x, scales, bias, out);
    quant_gemm_kernel<<<dim3(NN / 128, SPLITK), 128>>>(qw, (const float*)scales, out);
}